// round 15
// baseline (speedup 1.0000x reference)
#include <cuda_runtime.h>
#include <cstddef>

// HBV fused time-scan — BALANCED 2-role warp specialization.
// Block 256 thr x 79 CTAs. Per SMSP: 1 "soil" warp (pure MUFU chain, stall-heavy,
// ~15 issue/step) + 1 "back" warp (loads+snow+routing+stores, issue-heavy,
// ~110 issue/step). Complementary residency; per-step pace = max(~85, ~125).
// Rings: RT/PE depth 3 (snow@e -> soil@e+1 -> routing@e+2), SMN depth 2.
// 730 = 73 chunks x 10; 75 epochs, one __syncthreads each.

#define NSTEP  730
#define NGRID  10000
#define PFD    10
#define NCHUNK 73
#define NEPOCH (NCHUNK + 2)
#define ROWX   (NGRID*3)
#define NEARZERO 1e-5f

__device__ __forceinline__ float fast_exp2(float v) {
    float r;
    asm("ex2.approx.ftz.f32 %0, %1;" : "=f"(r) : "f"(v));
    return r;   // MUFU.EX2
}

__global__ __launch_bounds__(256, 1)
void hbv_kernel(const float* __restrict__ x,
                const float* __restrict__ params,
                float* __restrict__ out)
{
    const int  tid   = threadIdx.x;
    const bool front = (tid < 128);          // warps 0-3: soil ; warps 4-7: back
    const int  l     = tid & 127;
    const int  cell  = blockIdx.x * 128 + l;
    const bool valid = (cell < NGRID);
    const int  cellc = valid ? cell : (NGRID - 1);

    __shared__ float RT [3][PFD][128];       // rain+tosoil, per chunk ring
    __shared__ float PE [3][PFD][128];       // PET, per chunk ring
    __shared__ float SMN[2][PFD][128];       // soil SMn, per chunk ring

    const float* p = params + ((size_t)(NSTEP - 1) * NGRID + (size_t)cellc) * 12;
    const float BETA    = 1.0f   + p[0]  * 5.0f;
    const float FC      = 50.0f  + p[1]  * 950.0f;
    const float K0      = 0.05f  + p[2]  * 0.85f;
    const float K1      = 0.01f  + p[3]  * 0.49f;
    const float K2      = 0.001f + p[4]  * 0.199f;
    const float LP      = 0.2f   + p[5]  * 0.8f;
    const float PERCmax =          p[6]  * 10.0f;
    const float UZL     =          p[7]  * 100.0f;
    const float TT      = -2.5f  + p[8]  * 5.0f;
    const float CFMAX   = 0.5f   + p[9]  * 9.5f;
    const float CFR     =          p[10] * 0.1f;
    const float CWH     =          p[11] * 0.2f;

    const float invLPFC     = 1.0f / (LP * FC);
    const float betaLgInvFC = BETA * __log2f(1.0f / FC);   // (SM/FC)^B = exp2(B*lgSM + this)
    const float K1m         = 1.0f - K1;
    const float K01         = K0 * K1m;                    // Q0+Q1 = K01*u + K1*s1

    const size_t n = (size_t)NSTEP * NGRID;

    if (front) {
        // ================= SOIL warp: chunk e-1 at epoch e =================
        float SM = 0.001f;
        for (int e = 0; e < NEPOCH; ++e) {
            if (e >= 1 && e <= NCHUNK) {
                const int c  = e - 1;
                const int rs = c % 3;
                const int ws = c & 1;
                // stage inputs first (hoisted LDS, latency off the chain)
                float rt[PFD], pe[PFD];
#pragma unroll
                for (int j = 0; j < PFD; ++j) {
                    rt[j] = RT[rs][j][l];
                    pe[j] = PE[rs][j][l];
                }
#pragma unroll
                for (int j = 0; j < PFD; ++j) {
                    const float c1  = pe[j] * invLPFC;
                    const float lg  = __log2f(SM);
                    const float sw  = fast_exp2(fmaf(BETA, lg, betaLgInvFC));
                    const float a   = SM + rt[j];
                    const float SMn = fmaxf(fmaf(-rt[j], sw, a), SM);   // min(sw,1) folded
                    SM = fmaxf(fmaxf(fmaf(-c1, SMn, SMn), SMn - pe[j]), NEARZERO);
                    SMN[ws][j][l] = SMn;
                }
            }
            __syncthreads();
        }
    } else {
        // ================= BACK warp: loads + snow(e) + routing(e-2) =================
        float SNOWPACK = 0.001f, MELTWATER = 0.001f;
        float SMprev = 0.001f, SUZ = 0.001f, SLZ = 0.001f;
        float bP[PFD], bT[PFD], bE[PFD], nP[PFD], nT[PFD], nE[PFD];
        const float* xb = x + (size_t)cellc * 3;
        float* sp = out + 2 * n + cellc;      // SWE   (chunk e rows)
        float* qp = out + cellc;              // Qsim  (chunk e-2 rows)
        float* ap = out + n + cellc;          // AET

        // prologue: chunk 0 inputs (rows 0..9)
#pragma unroll
        for (int j = 0; j < PFD; ++j) {
            bP[j] = xb[j * ROWX];
            bT[j] = xb[j * ROWX + 1];
            bE[j] = xb[j * ROWX + 2];
        }

        for (int e = 0; e < NEPOCH; ++e) {
            // ---- snow for chunk e ----
            if (e < NCHUNK) {
                if (e < NCHUNK - 1) {          // prefetch chunk e+1
#pragma unroll
                    for (int j = 0; j < PFD; ++j) {
                        nP[j] = xb[(PFD + j) * ROWX];
                        nT[j] = xb[(PFD + j) * ROWX + 1];
                        nE[j] = xb[(PFD + j) * ROWX + 2];
                    }
                }
                const int rs = e % 3;
#pragma unroll
                for (int j = 0; j < PFD; ++j) {
                    const float Pt = bP[j], Tt = bT[j], Et = bE[j];
                    const float RAIN = (Tt >= TT) ? Pt : 0.0f;
                    const float m    = CFMAX * (Tt - TT);
                    const float sel  = (m >= 0.0f) ? m : (CFR * m);    // melt / -refreeze
                    const float SP1  = SNOWPACK + (Pt - RAIN);
                    const float nn   = fminf(fmaxf(sel, -MELTWATER), SP1);
                    SNOWPACK  = SP1 - nn;
                    MELTWATER = MELTWATER + nn;
                    const float tosoil = fmaxf(fmaf(-CWH, SNOWPACK, MELTWATER), 0.0f);
                    MELTWATER -= tosoil;
                    RT[rs][j][l] = RAIN + tosoil;
                    PE[rs][j][l] = Et;
                    if (valid) sp[j * NGRID] = SNOWPACK;
                }
#pragma unroll
                for (int j = 0; j < PFD; ++j) { bP[j]=nP[j]; bT[j]=nT[j]; bE[j]=nE[j]; }
                xb += PFD * ROWX;
                sp += PFD * NGRID;
            }
            // ---- routing for chunk e-2 (recompute rech/ET from SMn) ----
            if (e >= 2) {
                const int c   = e - 2;
                const int rs2 = c % 3;
                const int ss  = c & 1;
#pragma unroll
                for (int j = 0; j < PFD; ++j) {
                    const float SMn  = SMN[ss][j][l];
                    const float rt   = RT[rs2][j][l];
                    const float PETv = PE[rs2][j][l];
                    const float c1   = PETv * invLPFC;
                    const float a    = SMprev + rt;
                    const float rex  = (a - SMn) + fmaxf(SMn - FC, 0.0f);  // rech+excess
                    const float ET   = fminf(fminf(SMn * c1, PETv), SMn);
                    SMprev = fmaxf(fmaxf(fmaf(-c1, SMn, SMn), SMn - PETv), NEARZERO);
                    const float SUZa = SUZ + rex;
                    const float PERC = fminf(SUZa, PERCmax);
                    const float s1   = SUZa - PERC;
                    const float u    = fmaxf(s1 - UZL, 0.0f);
                    const float t1   = K01 * u;
                    const float Q01  = fmaf(K1, s1, t1);
                    SUZ = fmaf(K1m, s1, -t1);
                    SLZ += PERC;
                    const float Q2 = K2 * SLZ;
                    SLZ -= Q2;
                    if (valid) { qp[j * NGRID] = Q01 + Q2; ap[j * NGRID] = ET; }
                }
                qp += PFD * NGRID;
                ap += PFD * NGRID;
            }
            __syncthreads();
        }
    }
}

extern "C" void kernel_launch(void* const* d_in, const int* in_sizes, int n_in,
                              void* d_out, int out_size)
{
    const float* x      = (const float*)d_in[0];
    const float* params = (const float*)d_in[1];
    float* out          = (float*)d_out;

    const int blocks = (NGRID + 127) / 128;   // 79 CTAs x 256 threads
    hbv_kernel<<<blocks, 256>>>(x, params, out);
}